// round 10
// baseline (speedup 1.0000x reference)
#include <cuda_runtime.h>
#include <math.h>

// Problem constants
#define BB 16
#define CC 512
#define NN 1024   // H*W
#define GG 32
#define CG 16     // CC/GG
#define TEXT 180
#define FF 1024
#define EPSV 1e-6f
#define SCALE 0.04419417382415922f   // 512^-0.5
#define ROWS 64

// ---- scratch (static device memory) ----
__device__ float d_wgpart[16 * CC];   // per-slab wq column-sum partials
__device__ float d_wosum[CC];
__device__ float d_wgsum[GG];
__device__ float d_c0part[GG];
__device__ float d_bqsum;
__device__ float d_k[BB*FF];
__device__ float d_v[BB*FF];
__device__ float d_psum[BB*GG*4];     // per-quarter stats partials
__device__ float d_psum2[BB*GG*4];
__device__ __align__(16) float d_P[BB*GG*NN];  // 2 MB
__device__ __align__(16) float d_h2[BB*NN];

// ============================================================
// Kernel 0: prep — weight sums + k/v projections
//   blocks 0..15  : wq colsum partials (32 rows each)
//   blocks 16..79 : k/v projections
//   blocks 80..87 : wo row sums
//   block  88     : bq sum
// ============================================================
__global__ void prep_kernel(const float* __restrict__ cond,
                            const float* __restrict__ wq,
                            const float* __restrict__ bq,
                            const float* __restrict__ wk,
                            const float* __restrict__ bk,
                            const float* __restrict__ wv,
                            const float* __restrict__ bv,
                            const float* __restrict__ wo)
{
    int blk = blockIdx.x;
    int tid = threadIdx.x;

    if (blk < 16) {
        // wq colsum partial over rows [32*blk, 32*blk+32)
        __shared__ float4 shp[128];
        const float4* wq4 = (const float4*)wq;
        int col4 = tid & 127;
        int rg   = tid >> 7;   // 0 or 1
        float4 pa = make_float4(0.f, 0.f, 0.f, 0.f);
        int r0 = blk * 32 + rg * 16;
        #pragma unroll
        for (int i = 0; i < 16; i++) {
            float4 w = wq4[(r0 + i) * 128 + col4];
            pa.x += w.x; pa.y += w.y; pa.z += w.z; pa.w += w.w;
        }
        if (rg == 1) shp[col4] = pa;
        __syncthreads();
        if (rg == 0) {
            float4 t = shp[col4];
            pa.x += t.x; pa.y += t.y; pa.z += t.z; pa.w += t.w;
            ((float4*)d_wgpart)[blk * 128 + col4] = pa;
        }
    } else if (blk < 80) {
        // k/v projection
        __shared__ float cs[TEXT];
        int blk2 = blk - 16;
        int b = blk2 >> 2;
        int f = ((blk2 & 3) << 8) + tid;
        if (tid < TEXT) cs[tid] = cond[b * TEXT + tid];
        __syncthreads();
        float ak = bk[f], av = bv[f];
        const float4* wkr = (const float4*)(wk + (size_t)f * TEXT);
        const float4* wvr = (const float4*)(wv + (size_t)f * TEXT);
        const float4* cs4 = (const float4*)cs;
        #pragma unroll 5
        for (int t = 0; t < TEXT / 4; t++) {
            float4 c  = cs4[t];
            float4 k4 = wkr[t];
            float4 v4 = wvr[t];
            ak = fmaf(c.x, k4.x, ak); ak = fmaf(c.y, k4.y, ak);
            ak = fmaf(c.z, k4.z, ak); ak = fmaf(c.w, k4.w, ak);
            av = fmaf(c.x, v4.x, av); av = fmaf(c.y, v4.y, av);
            av = fmaf(c.z, v4.z, av); av = fmaf(c.w, v4.w, av);
        }
        d_k[b * FF + f] = ak;
        d_v[b * FF + f] = av;
    } else if (blk < 88) {
        // wo row sums
        int blk3 = blk - 80;
        int warp = tid >> 5, lane = tid & 31;
        int o = blk3 * 64 + warp * 8;
        #pragma unroll
        for (int j = 0; j < 8; j++) {
            const float4* wr = (const float4*)(wo + (size_t)(o + j) * CC);
            float s = 0.f;
            #pragma unroll
            for (int c = 0; c < 4; c++) {
                float4 v = wr[lane + c * 32];
                s += v.x + v.y + v.z + v.w;
            }
            #pragma unroll
            for (int off = 16; off > 0; off >>= 1)
                s += __shfl_down_sync(0xffffffffu, s, off);
            if (lane == 0) d_wosum[o + j] = s;
        }
    } else {
        if (tid < 32) {
            float s = 0.f;
            #pragma unroll
            for (int i = 0; i < CC / 32; i++) s += bq[tid + i * 32];
            #pragma unroll
            for (int off = 16; off > 0; off >>= 1)
                s += __shfl_down_sync(0xffffffffu, s, off);
            if (tid == 0) d_bqsum = s;
        }
    }
}

// ============================================================
// Kernel 1: gn — pure streaming pass over x
// grid 2048 (= B*G*4), block = (bg, quarter of n): 16 ch x 256 n
// ============================================================
__global__ void gn_kernel(const float* __restrict__ x,
                          const float* __restrict__ gamma,
                          const float* __restrict__ beta)
{
    __shared__ float wtmp[16][17];
    __shared__ float colsum_s[16];
    __shared__ float wgs[16];
    __shared__ float4 sh4[4][64];
    __shared__ float sw[8], sw2[8];

    int blk = blockIdx.x;
    int tid = threadIdx.x;
    int bg = blk >> 2, q = blk & 3;
    int b = bg >> 5, g = bg & 31;
    int c0 = g * CG;
    int hi = tid >> 6, lo = tid & 63;
    int warp = tid >> 5, lane = tid & 31;

    // finalize wg for this group from slab partials (1 L2 load/thread)
    {
        int s_idx = tid >> 4, c_idx = tid & 15;
        wtmp[s_idx][c_idx] = d_wgpart[s_idx * CC + c0 + c_idx];
    }
    __syncthreads();
    if (tid < 16) {
        float s = 0.f;
        #pragma unroll
        for (int i = 0; i < 16; i++) s += wtmp[i][tid];
        colsum_s[tid] = s;
        wgs[tid] = s * gamma[c0 + tid];
    }
    __syncthreads();

    // one block per group publishes group constants
    if (bg < 32 && q == 0 && tid == 0) {
        float cs = 0.f, ws = 0.f;
        #pragma unroll
        for (int c = 0; c < CG; c++) {
            cs += colsum_s[c] * beta[c0 + c];
            ws += wgs[c];
        }
        d_c0part[g] = cs;
        d_wgsum[g]  = ws;
    }

    // --- main stream: 4 independent float4 loads (4 channels, same n) ---
    const float4* x4 = (const float4*)x + (size_t)(b * CC + c0) * 256 + q * 64;

    float4 xv[4];
    #pragma unroll
    for (int j = 0; j < 4; j++)
        xv[j] = x4[(hi + 4 * j) * 256 + lo];

    float4 pn = make_float4(0.f, 0.f, 0.f, 0.f);
    float s = 0.f, s2 = 0.f;
    #pragma unroll
    for (int j = 0; j < 4; j++) {
        float w = wgs[hi + 4 * j];
        float4 v = xv[j];
        pn.x = fmaf(w, v.x, pn.x);
        pn.y = fmaf(w, v.y, pn.y);
        pn.z = fmaf(w, v.z, pn.z);
        pn.w = fmaf(w, v.w, pn.w);
        s  += v.x + v.y + v.z + v.w;
        s2 += v.x*v.x + v.y*v.y + v.z*v.z + v.w*v.w;
    }

    // reduce P across the 4 channel-subsets
    sh4[hi][lo] = pn;

    // warp-level stats reduction
    #pragma unroll
    for (int off = 16; off > 0; off >>= 1) {
        s  += __shfl_xor_sync(0xffffffffu, s,  off);
        s2 += __shfl_xor_sync(0xffffffffu, s2, off);
    }
    if (lane == 0) { sw[warp] = s; sw2[warp] = s2; }
    __syncthreads();

    if (tid < 64) {
        float4 a = sh4[0][tid], b1 = sh4[1][tid], c1 = sh4[2][tid], d1 = sh4[3][tid];
        float4 r;
        r.x = a.x + b1.x + c1.x + d1.x;
        r.y = a.y + b1.y + c1.y + d1.y;
        r.z = a.z + b1.z + c1.z + d1.z;
        r.w = a.w + b1.w + c1.w + d1.w;
        ((float4*)d_P)[bg * 256 + q * 64 + tid] = r;
    }
    if (tid == 0) {
        float ts = 0.f, ts2 = 0.f;
        #pragma unroll
        for (int i = 0; i < 8; i++) { ts += sw[i]; ts2 += sw2[i]; }
        d_psum[blk]  = ts;
        d_psum2[blk] = ts2;
    }
}

// ============================================================
// Kernel 2: softmax mixture -> h2[b,n]
// grid 256, one warp per n-row
// ============================================================
__global__ void attn_kernel()
{
    int blk = blockIdx.x;
    int b  = blk >> 4;
    int n0 = (blk & 15) * ROWS;
    int tid = threadIdx.x;
    int warp = tid >> 5, lane = tid & 31;

    __shared__ float ks[FF], vs[FF];
    __shared__ float Ps[GG][ROWS + 1];
    __shared__ float Ss[ROWS];
    __shared__ float rstd_s[GG];
    __shared__ float red[20];

    for (int i = tid; i < FF; i += 256) {
        ks[i] = d_k[b * FF + i];
        vs[i] = d_v[b * FF + i];
    }
    for (int i = tid; i < GG * ROWS; i += 256) {
        int g = i >> 6, nn = i & (ROWS - 1);
        Ps[g][nn] = d_P[(size_t)(b * GG + g) * NN + n0 + nn];
    }
    // finalize group stats from per-quarter partials
    float mu_l = 0.f;
    if (tid < GG) {
        int base = (b * GG + tid) * 4;
        float ps  = (d_psum [base] + d_psum [base + 1])
                  + (d_psum [base + 2] + d_psum [base + 3]);
        float ps2 = (d_psum2[base] + d_psum2[base + 1])
                  + (d_psum2[base + 2] + d_psum2[base + 3]);
        float mean = ps * (1.f / 16384.f);
        float var  = ps2 * (1.f / 16384.f) - mean * mean;
        rstd_s[tid] = rsqrtf(var + EPSV);
        mu_l = mean;
    }
    __syncthreads();

    // per-b kmax/kmin + T[b]
    float km = -1e30f, kn = 1e30f;
    for (int i = tid; i < FF; i += 256) {
        float kk = ks[i];
        km = fmaxf(km, kk);
        kn = fminf(kn, kk);
    }
    #pragma unroll
    for (int off = 16; off > 0; off >>= 1) {
        km = fmaxf(km, __shfl_xor_sync(0xffffffffu, km, off));
        kn = fminf(kn, __shfl_xor_sync(0xffffffffu, kn, off));
    }
    if (lane == 0) { red[warp] = km; red[8 + warp] = kn; }
    float Tp = 0.f;
    if (tid < GG)
        Tp = -mu_l * rstd_s[tid] * d_wgsum[tid] + d_c0part[tid];
    if (warp == 0) {
        #pragma unroll
        for (int off = 16; off > 0; off >>= 1)
            Tp += __shfl_xor_sync(0xffffffffu, Tp, off);
        if (lane == 0) red[16] = Tp + d_bqsum;
    }
    __syncthreads();

    float kmax = red[0], kmin = red[8];
    #pragma unroll
    for (int i = 1; i < 8; i++) {
        kmax = fmaxf(kmax, red[i]);
        kmin = fminf(kmin, red[8 + i]);
    }
    float Tc = red[16];

    if (tid < ROWS) {
        float s = Tc;
        #pragma unroll
        for (int g = 0; g < GG; g++) s = fmaf(rstd_s[g], Ps[g][tid], s);
        Ss[tid] = SCALE * s;
    }
    __syncthreads();

    for (int r = warp; r < ROWS; r += 8) {
        float a = Ss[r];
        float shift = (a >= 0.f) ? a * kmax : a * kmin;
        float num = 0.f, den = 0.f;
        #pragma unroll
        for (int f = lane; f < FF; f += 32) {
            float e = __expf(fmaf(a, ks[f], -shift));
            den += e;
            num = fmaf(vs[f], e, num);
        }
        #pragma unroll
        for (int off = 16; off > 0; off >>= 1) {
            num += __shfl_xor_sync(0xffffffffu, num, off);
            den += __shfl_xor_sync(0xffffffffu, den, off);
        }
        if (lane == 0) d_h2[b * NN + n0 + r] = num / den;
    }
}

// ============================================================
// Kernel 3: y = x + h2[b,n]*wosum[o] + bo[o]  — ILP=2, grid 4096, ldcs/stcs
// ============================================================
__global__ void out_kernel(const float* __restrict__ x,
                           const float* __restrict__ bo,
                           float* __restrict__ y)
{
    int blk = blockIdx.x;
    int tid = threadIdx.x;
    int b  = blk >> 8;            // 256 blocks per batch
    int o0 = (blk & 255) << 1;    // 2 consecutive o rows

    float4 h2 = ((const float4*)d_h2)[b * 256 + tid];

    size_t base = (size_t)(b * CC + o0) * 256 + tid;
    const float4* xr = (const float4*)x + base;
    float4*       yr = (float4*)y + base;

    float4 xv0 = __ldcs(xr);          // last use of x: evict-first
    float4 xv1 = __ldcs(xr + 256);

    float ws0 = d_wosum[o0],     bb0 = bo[o0];
    float ws1 = d_wosum[o0 + 1], bb1 = bo[o0 + 1];

    float4 r0, r1;
    r0.x = fmaf(h2.x, ws0, xv0.x + bb0);
    r0.y = fmaf(h2.y, ws0, xv0.y + bb0);
    r0.z = fmaf(h2.z, ws0, xv0.z + bb0);
    r0.w = fmaf(h2.w, ws0, xv0.w + bb0);
    r1.x = fmaf(h2.x, ws1, xv1.x + bb1);
    r1.y = fmaf(h2.y, ws1, xv1.y + bb1);
    r1.z = fmaf(h2.z, ws1, xv1.z + bb1);
    r1.w = fmaf(h2.w, ws1, xv1.w + bb1);

    __stcs(yr, r0);          // streaming store: evict-first
    __stcs(yr + 256, r1);
}

// ============================================================
extern "C" void kernel_launch(void* const* d_in, const int* in_sizes, int n_in,
                              void* d_out, int out_size)
{
    const float* x     = (const float*)d_in[0];
    const float* cond  = (const float*)d_in[1];
    const float* gamma = (const float*)d_in[2];
    const float* beta  = (const float*)d_in[3];
    const float* wq    = (const float*)d_in[4];
    const float* bq    = (const float*)d_in[5];
    const float* wk    = (const float*)d_in[6];
    const float* bk    = (const float*)d_in[7];
    const float* wv    = (const float*)d_in[8];
    const float* bv    = (const float*)d_in[9];
    const float* wo    = (const float*)d_in[10];
    const float* bo    = (const float*)d_in[11];
    float* y = (float*)d_out;

    prep_kernel<<<89, 256>>>(cond, wq, bq, wk, bk, wv, bv, wo);
    gn_kernel<<<BB * GG * 4, 256>>>(x, gamma, beta);
    attn_kernel<<<BB * (NN / ROWS), 256>>>();
    out_kernel<<<(BB * CC) / 2, 256>>>(x, bo, y);
}

// round 11
// speedup vs baseline: 1.3513x; 1.3513x over previous
#include <cuda_runtime.h>
#include <math.h>

// Problem constants
#define BB 16
#define CC 512
#define NN 1024   // H*W
#define GG 32
#define CG 16     // CC/GG
#define TEXT 180
#define FF 1024
#define EPSV 1e-6f
#define SCALE 0.04419417382415922f   // 512^-0.5
#define ROWS 64

// ---- scratch (static device memory) ----
__device__ float d_wgpart[16 * CC];   // per-slab wq column-sum partials
__device__ float d_wosum[CC];
__device__ float d_wgsum[GG];
__device__ float d_c0part[GG];
__device__ float d_bqsum;
__device__ float d_k[BB*FF];
__device__ float d_v[BB*FF];
__device__ float d_psum[BB*GG*4];     // per-quarter stats partials
__device__ float d_psum2[BB*GG*4];
__device__ __align__(16) float d_P[BB*GG*NN];  // 2 MB
__device__ __align__(16) float d_h2[BB*NN];

// ============================================================
// Kernel 0: prep — weight sums + k/v projections
//   blocks 0..15  : wq colsum partials (32 rows each)
//   blocks 16..79 : k/v projections
//   blocks 80..87 : wo row sums
//   block  88     : bq sum
// ============================================================
__global__ void prep_kernel(const float* __restrict__ cond,
                            const float* __restrict__ wq,
                            const float* __restrict__ bq,
                            const float* __restrict__ wk,
                            const float* __restrict__ bk,
                            const float* __restrict__ wv,
                            const float* __restrict__ bv,
                            const float* __restrict__ wo)
{
    int blk = blockIdx.x;
    int tid = threadIdx.x;

    if (blk < 16) {
        // wq colsum partial over rows [32*blk, 32*blk+32)
        __shared__ float4 shp[128];
        const float4* wq4 = (const float4*)wq;
        int col4 = tid & 127;
        int rg   = tid >> 7;   // 0 or 1
        float4 pa = make_float4(0.f, 0.f, 0.f, 0.f);
        int r0 = blk * 32 + rg * 16;
        #pragma unroll
        for (int i = 0; i < 16; i++) {
            float4 w = wq4[(r0 + i) * 128 + col4];
            pa.x += w.x; pa.y += w.y; pa.z += w.z; pa.w += w.w;
        }
        if (rg == 1) shp[col4] = pa;
        __syncthreads();
        if (rg == 0) {
            float4 t = shp[col4];
            pa.x += t.x; pa.y += t.y; pa.z += t.z; pa.w += t.w;
            ((float4*)d_wgpart)[blk * 128 + col4] = pa;
        }
    } else if (blk < 80) {
        // k/v projection
        __shared__ float cs[TEXT];
        int blk2 = blk - 16;
        int b = blk2 >> 2;
        int f = ((blk2 & 3) << 8) + tid;
        if (tid < TEXT) cs[tid] = cond[b * TEXT + tid];
        __syncthreads();
        float ak = bk[f], av = bv[f];
        const float4* wkr = (const float4*)(wk + (size_t)f * TEXT);
        const float4* wvr = (const float4*)(wv + (size_t)f * TEXT);
        const float4* cs4 = (const float4*)cs;
        #pragma unroll 5
        for (int t = 0; t < TEXT / 4; t++) {
            float4 c  = cs4[t];
            float4 k4 = wkr[t];
            float4 v4 = wvr[t];
            ak = fmaf(c.x, k4.x, ak); ak = fmaf(c.y, k4.y, ak);
            ak = fmaf(c.z, k4.z, ak); ak = fmaf(c.w, k4.w, ak);
            av = fmaf(c.x, v4.x, av); av = fmaf(c.y, v4.y, av);
            av = fmaf(c.z, v4.z, av); av = fmaf(c.w, v4.w, av);
        }
        d_k[b * FF + f] = ak;
        d_v[b * FF + f] = av;
    } else if (blk < 88) {
        // wo row sums
        int blk3 = blk - 80;
        int warp = tid >> 5, lane = tid & 31;
        int o = blk3 * 64 + warp * 8;
        #pragma unroll
        for (int j = 0; j < 8; j++) {
            const float4* wr = (const float4*)(wo + (size_t)(o + j) * CC);
            float s = 0.f;
            #pragma unroll
            for (int c = 0; c < 4; c++) {
                float4 v = wr[lane + c * 32];
                s += v.x + v.y + v.z + v.w;
            }
            #pragma unroll
            for (int off = 16; off > 0; off >>= 1)
                s += __shfl_down_sync(0xffffffffu, s, off);
            if (lane == 0) d_wosum[o + j] = s;
        }
    } else {
        if (tid < 32) {
            float s = 0.f;
            #pragma unroll
            for (int i = 0; i < CC / 32; i++) s += bq[tid + i * 32];
            #pragma unroll
            for (int off = 16; off > 0; off >>= 1)
                s += __shfl_down_sync(0xffffffffu, s, off);
            if (tid == 0) d_bqsum = s;
        }
    }
}

// ============================================================
// Kernel 1: gn — pure streaming pass over x
// grid 2048 (= B*G*4), block = (bg, quarter of n): 16 ch x 256 n
// ============================================================
__global__ void gn_kernel(const float* __restrict__ x,
                          const float* __restrict__ gamma,
                          const float* __restrict__ beta)
{
    __shared__ float wtmp[16][17];
    __shared__ float colsum_s[16];
    __shared__ float wgs[16];
    __shared__ float4 sh4[4][64];
    __shared__ float sw[8], sw2[8];

    int blk = blockIdx.x;
    int tid = threadIdx.x;
    int bg = blk >> 2, q = blk & 3;
    int b = bg >> 5, g = bg & 31;
    int c0 = g * CG;
    int hi = tid >> 6, lo = tid & 63;
    int warp = tid >> 5, lane = tid & 31;

    // finalize wg for this group from slab partials (1 L2 load/thread)
    {
        int s_idx = tid >> 4, c_idx = tid & 15;
        wtmp[s_idx][c_idx] = d_wgpart[s_idx * CC + c0 + c_idx];
    }
    __syncthreads();
    if (tid < 16) {
        float s = 0.f;
        #pragma unroll
        for (int i = 0; i < 16; i++) s += wtmp[i][tid];
        colsum_s[tid] = s;
        wgs[tid] = s * gamma[c0 + tid];
    }
    __syncthreads();

    // one block per group publishes group constants
    if (bg < 32 && q == 0 && tid == 0) {
        float cs = 0.f, ws = 0.f;
        #pragma unroll
        for (int c = 0; c < CG; c++) {
            cs += colsum_s[c] * beta[c0 + c];
            ws += wgs[c];
        }
        d_c0part[g] = cs;
        d_wgsum[g]  = ws;
    }

    // --- main stream: 4 independent float4 loads (4 channels, same n) ---
    const float4* x4 = (const float4*)x + (size_t)(b * CC + c0) * 256 + q * 64;

    float4 xv[4];
    #pragma unroll
    for (int j = 0; j < 4; j++)
        xv[j] = x4[(hi + 4 * j) * 256 + lo];

    float4 pn = make_float4(0.f, 0.f, 0.f, 0.f);
    float s = 0.f, s2 = 0.f;
    #pragma unroll
    for (int j = 0; j < 4; j++) {
        float w = wgs[hi + 4 * j];
        float4 v = xv[j];
        pn.x = fmaf(w, v.x, pn.x);
        pn.y = fmaf(w, v.y, pn.y);
        pn.z = fmaf(w, v.z, pn.z);
        pn.w = fmaf(w, v.w, pn.w);
        s  += v.x + v.y + v.z + v.w;
        s2 += v.x*v.x + v.y*v.y + v.z*v.z + v.w*v.w;
    }

    // reduce P across the 4 channel-subsets
    sh4[hi][lo] = pn;

    // warp-level stats reduction
    #pragma unroll
    for (int off = 16; off > 0; off >>= 1) {
        s  += __shfl_xor_sync(0xffffffffu, s,  off);
        s2 += __shfl_xor_sync(0xffffffffu, s2, off);
    }
    if (lane == 0) { sw[warp] = s; sw2[warp] = s2; }
    __syncthreads();

    if (tid < 64) {
        float4 a = sh4[0][tid], b1 = sh4[1][tid], c1 = sh4[2][tid], d1 = sh4[3][tid];
        float4 r;
        r.x = a.x + b1.x + c1.x + d1.x;
        r.y = a.y + b1.y + c1.y + d1.y;
        r.z = a.z + b1.z + c1.z + d1.z;
        r.w = a.w + b1.w + c1.w + d1.w;
        ((float4*)d_P)[bg * 256 + q * 64 + tid] = r;
    }
    if (tid == 0) {
        float ts = 0.f, ts2 = 0.f;
        #pragma unroll
        for (int i = 0; i < 8; i++) { ts += sw[i]; ts2 += sw2[i]; }
        d_psum[blk]  = ts;
        d_psum2[blk] = ts2;
    }
}

// ============================================================
// Kernel 2: softmax mixture -> h2[b,n]
// grid 256, one warp per n-row
// ============================================================
__global__ void attn_kernel()
{
    int blk = blockIdx.x;
    int b  = blk >> 4;
    int n0 = (blk & 15) * ROWS;
    int tid = threadIdx.x;
    int warp = tid >> 5, lane = tid & 31;

    __shared__ float ks[FF], vs[FF];
    __shared__ float Ps[GG][ROWS + 1];
    __shared__ float Ss[ROWS];
    __shared__ float rstd_s[GG];
    __shared__ float red[20];

    for (int i = tid; i < FF; i += 256) {
        ks[i] = d_k[b * FF + i];
        vs[i] = d_v[b * FF + i];
    }
    for (int i = tid; i < GG * ROWS; i += 256) {
        int g = i >> 6, nn = i & (ROWS - 1);
        Ps[g][nn] = d_P[(size_t)(b * GG + g) * NN + n0 + nn];
    }
    // finalize group stats from per-quarter partials
    float mu_l = 0.f;
    if (tid < GG) {
        int base = (b * GG + tid) * 4;
        float ps  = (d_psum [base] + d_psum [base + 1])
                  + (d_psum [base + 2] + d_psum [base + 3]);
        float ps2 = (d_psum2[base] + d_psum2[base + 1])
                  + (d_psum2[base + 2] + d_psum2[base + 3]);
        float mean = ps * (1.f / 16384.f);
        float var  = ps2 * (1.f / 16384.f) - mean * mean;
        rstd_s[tid] = rsqrtf(var + EPSV);
        mu_l = mean;
    }
    __syncthreads();

    // per-b kmax/kmin + T[b]
    float km = -1e30f, kn = 1e30f;
    for (int i = tid; i < FF; i += 256) {
        float kk = ks[i];
        km = fmaxf(km, kk);
        kn = fminf(kn, kk);
    }
    #pragma unroll
    for (int off = 16; off > 0; off >>= 1) {
        km = fmaxf(km, __shfl_xor_sync(0xffffffffu, km, off));
        kn = fminf(kn, __shfl_xor_sync(0xffffffffu, kn, off));
    }
    if (lane == 0) { red[warp] = km; red[8 + warp] = kn; }
    float Tp = 0.f;
    if (tid < GG)
        Tp = -mu_l * rstd_s[tid] * d_wgsum[tid] + d_c0part[tid];
    if (warp == 0) {
        #pragma unroll
        for (int off = 16; off > 0; off >>= 1)
            Tp += __shfl_xor_sync(0xffffffffu, Tp, off);
        if (lane == 0) red[16] = Tp + d_bqsum;
    }
    __syncthreads();

    float kmax = red[0], kmin = red[8];
    #pragma unroll
    for (int i = 1; i < 8; i++) {
        kmax = fmaxf(kmax, red[i]);
        kmin = fminf(kmin, red[8 + i]);
    }
    float Tc = red[16];

    if (tid < ROWS) {
        float s = Tc;
        #pragma unroll
        for (int g = 0; g < GG; g++) s = fmaf(rstd_s[g], Ps[g][tid], s);
        Ss[tid] = SCALE * s;
    }
    __syncthreads();

    for (int r = warp; r < ROWS; r += 8) {
        float a = Ss[r];
        float shift = (a >= 0.f) ? a * kmax : a * kmin;
        float num = 0.f, den = 0.f;
        #pragma unroll
        for (int f = lane; f < FF; f += 32) {
            float e = __expf(fmaf(a, ks[f], -shift));
            den += e;
            num = fmaf(vs[f], e, num);
        }
        #pragma unroll
        for (int off = 16; off > 0; off >>= 1) {
            num += __shfl_xor_sync(0xffffffffu, num, off);
            den += __shfl_xor_sync(0xffffffffu, den, off);
        }
        if (lane == 0) d_h2[b * NN + n0 + r] = num / den;
    }
}

// ============================================================
// Kernel 3: y = x + h2[b,n]*wosum[o] + bo[o]
// R1 config: ILP=1, grid 8192, plain loads/stores (best measured: 11.2us)
// ============================================================
__global__ void out_kernel(const float* __restrict__ x,
                           const float* __restrict__ bo,
                           float* __restrict__ y)
{
    int i = blockIdx.x * 256 + threadIdx.x;   // over float4 (2,097,152)
    float4 xv = ((const float4*)x)[i];
    int n4   = i & 255;                       // NN/4 = 256
    int rest = i >> 8;
    int o = rest & 511;
    int b = rest >> 9;
    float4 h2 = ((const float4*)d_h2)[b * 256 + n4];
    float ws = d_wosum[o];
    float bias = bo[o];
    float4 r;
    r.x = fmaf(h2.x, ws, xv.x + bias);
    r.y = fmaf(h2.y, ws, xv.y + bias);
    r.z = fmaf(h2.z, ws, xv.z + bias);
    r.w = fmaf(h2.w, ws, xv.w + bias);
    ((float4*)y)[i] = r;
}

// ============================================================
extern "C" void kernel_launch(void* const* d_in, const int* in_sizes, int n_in,
                              void* d_out, int out_size)
{
    const float* x     = (const float*)d_in[0];
    const float* cond  = (const float*)d_in[1];
    const float* gamma = (const float*)d_in[2];
    const float* beta  = (const float*)d_in[3];
    const float* wq    = (const float*)d_in[4];
    const float* bq    = (const float*)d_in[5];
    const float* wk    = (const float*)d_in[6];
    const float* bk    = (const float*)d_in[7];
    const float* wv    = (const float*)d_in[8];
    const float* bv    = (const float*)d_in[9];
    const float* wo    = (const float*)d_in[10];
    const float* bo    = (const float*)d_in[11];
    float* y = (float*)d_out;

    prep_kernel<<<89, 256>>>(cond, wq, bq, wk, bk, wv, bv, wo);
    gn_kernel<<<BB * GG * 4, 256>>>(x, gamma, beta);
    attn_kernel<<<BB * (NN / ROWS), 256>>>();
    out_kernel<<<(BB * CC * NN) / (4 * 256), 256>>>(x, bo, y);
}

// round 12
// speedup vs baseline: 1.4833x; 1.0977x over previous
#include <cuda_runtime.h>
#include <math.h>

// Problem constants
#define BB 16
#define CC 512
#define NN 1024   // H*W
#define GG 32
#define CG 16     // CC/GG
#define TEXT 180
#define FF 1024
#define EPSV 1e-6f
#define SCALE 0.04419417382415922f   // 512^-0.5
#define ROWS 64

// ---- scratch (static device memory) ----
__device__ float d_wg[CC];        // final colsum[c]*gamma[c]
__device__ float d_wosum[CC];
__device__ float d_wgsum[GG];
__device__ float d_c0part[GG];
__device__ float d_bqsum;
__device__ float d_k[BB*FF];
__device__ float d_v[BB*FF];
__device__ float d_psum[BB*GG*2];     // per-half stats partials
__device__ float d_psum2[BB*GG*2];
__device__ __align__(16) float d_P[BB*GG*NN];  // 2 MB
__device__ __align__(16) float d_h2[BB*NN];

// ============================================================
// Kernel 0: prep — finalize ALL weight constants + k/v projections
//   blocks 0..15  : wq colsums for 32 columns each (final d_wg + group consts)
//   blocks 16..79 : k/v projections
//   blocks 80..87 : wo row sums
//   block  88     : bq sum
// ============================================================
__global__ void prep_kernel(const float* __restrict__ cond,
                            const float* __restrict__ gamma,
                            const float* __restrict__ beta,
                            const float* __restrict__ wq,
                            const float* __restrict__ bq,
                            const float* __restrict__ wk,
                            const float* __restrict__ bk,
                            const float* __restrict__ wv,
                            const float* __restrict__ bv,
                            const float* __restrict__ wo)
{
    int blk = blockIdx.x;
    int tid = threadIdx.x;

    if (blk < 16) {
        // columns [32*blk, 32*blk+32): full colsum over 512 rows
        __shared__ float4 swp[8][8];
        __shared__ float gpart[8][2];   // per-c4 (wgsum, c0part) partials

        const float4* wq4 = (const float4*)wq;
        int warp = tid >> 5, lane = tid & 31;
        int c4 = lane & 7;              // float4-column within block (0..7)
        int r  = tid >> 3;              // base row 0..31

        float4 pa = make_float4(0.f, 0.f, 0.f, 0.f);
        #pragma unroll
        for (int k = 0; k < 16; k++) {
            float4 w = wq4[(r + 32 * k) * 128 + blk * 8 + c4];
            pa.x += w.x; pa.y += w.y; pa.z += w.z; pa.w += w.w;
        }
        // reduce over the 4 row-slots within the warp (lane bits 3,4)
        #pragma unroll
        for (int off = 8; off <= 16; off <<= 1) {
            pa.x += __shfl_xor_sync(0xffffffffu, pa.x, off);
            pa.y += __shfl_xor_sync(0xffffffffu, pa.y, off);
            pa.z += __shfl_xor_sync(0xffffffffu, pa.z, off);
            pa.w += __shfl_xor_sync(0xffffffffu, pa.w, off);
        }
        if (lane < 8) swp[warp][c4] = pa;
        __syncthreads();

        if (tid < 8) {
            float4 cs = swp[0][tid];
            #pragma unroll
            for (int w = 1; w < 8; w++) {
                float4 t = swp[w][tid];
                cs.x += t.x; cs.y += t.y; cs.z += t.z; cs.w += t.w;
            }
            int gc4 = blk * 8 + tid;    // global float4 column
            float4 gm = ((const float4*)gamma)[gc4];
            float4 bt = ((const float4*)beta)[gc4];
            float4 wg;
            wg.x = cs.x * gm.x; wg.y = cs.y * gm.y;
            wg.z = cs.z * gm.z; wg.w = cs.w * gm.w;
            ((float4*)d_wg)[gc4] = wg;
            gpart[tid][0] = wg.x + wg.y + wg.z + wg.w;
            gpart[tid][1] = cs.x * bt.x + cs.y * bt.y + cs.z * bt.z + cs.w * bt.w;
        }
        __syncthreads();
        if (tid < 2) {
            // group 2*blk + tid covers c4 slots [4*tid, 4*tid+4)
            float ws = 0.f, cp = 0.f;
            #pragma unroll
            for (int i = 0; i < 4; i++) {
                ws += gpart[4 * tid + i][0];
                cp += gpart[4 * tid + i][1];
            }
            d_wgsum[2 * blk + tid]  = ws;
            d_c0part[2 * blk + tid] = cp;
        }
    } else if (blk < 80) {
        // k/v projection
        __shared__ float cs[TEXT];
        int blk2 = blk - 16;
        int b = blk2 >> 2;
        int f = ((blk2 & 3) << 8) + tid;
        if (tid < TEXT) cs[tid] = cond[b * TEXT + tid];
        __syncthreads();
        float ak = bk[f], av = bv[f];
        const float4* wkr = (const float4*)(wk + (size_t)f * TEXT);
        const float4* wvr = (const float4*)(wv + (size_t)f * TEXT);
        const float4* cs4 = (const float4*)cs;
        #pragma unroll 5
        for (int t = 0; t < TEXT / 4; t++) {
            float4 c  = cs4[t];
            float4 k4 = wkr[t];
            float4 v4 = wvr[t];
            ak = fmaf(c.x, k4.x, ak); ak = fmaf(c.y, k4.y, ak);
            ak = fmaf(c.z, k4.z, ak); ak = fmaf(c.w, k4.w, ak);
            av = fmaf(c.x, v4.x, av); av = fmaf(c.y, v4.y, av);
            av = fmaf(c.z, v4.z, av); av = fmaf(c.w, v4.w, av);
        }
        d_k[b * FF + f] = ak;
        d_v[b * FF + f] = av;
    } else if (blk < 88) {
        // wo row sums
        int blk3 = blk - 80;
        int warp = tid >> 5, lane = tid & 31;
        int o = blk3 * 64 + warp * 8;
        #pragma unroll
        for (int j = 0; j < 8; j++) {
            const float4* wr = (const float4*)(wo + (size_t)(o + j) * CC);
            float s = 0.f;
            #pragma unroll
            for (int c = 0; c < 4; c++) {
                float4 v = wr[lane + c * 32];
                s += v.x + v.y + v.z + v.w;
            }
            #pragma unroll
            for (int off = 16; off > 0; off >>= 1)
                s += __shfl_down_sync(0xffffffffu, s, off);
            if (lane == 0) d_wosum[o + j] = s;
        }
    } else {
        if (tid < 32) {
            float s = 0.f;
            #pragma unroll
            for (int i = 0; i < CC / 32; i++) s += bq[tid + i * 32];
            #pragma unroll
            for (int off = 16; off > 0; off >>= 1)
                s += __shfl_down_sync(0xffffffffu, s, off);
            if (tid == 0) d_bqsum = s;
        }
    }
}

// ============================================================
// Kernel 1: gn — pure streaming pass over x
// grid 1024 (= B*G*2), block = (bg, half of n): 16 ch x 512 n (32KB)
// Each thread: 8 batched float4 loads (8 channels, same n)
// ============================================================
__global__ void gn_kernel(const float* __restrict__ x)
{
    __shared__ float wgs[16];
    __shared__ float4 pshare[128];
    __shared__ float sw[8], sw2[8];

    int blk = blockIdx.x;
    int tid = threadIdx.x;
    int bg = blk >> 1, h = blk & 1;
    int b = bg >> 5, g = bg & 31;
    int c0 = g * CG;
    int hi = tid >> 7, lo = tid & 127;
    int warp = tid >> 5, lane = tid & 31;

    if (tid < 16) wgs[tid] = d_wg[c0 + tid];
    __syncthreads();

    // main stream: channels {hi, hi+2, ..., hi+14} at n4 = h*128 + lo
    const float4* x4 = (const float4*)x + (size_t)(b * CC + c0) * 256 + h * 128;

    float4 xv[8];
    #pragma unroll
    for (int j = 0; j < 8; j++)
        xv[j] = x4[(hi + 2 * j) * 256 + lo];

    float4 pn = make_float4(0.f, 0.f, 0.f, 0.f);
    float s = 0.f, s2 = 0.f;
    #pragma unroll
    for (int j = 0; j < 8; j++) {
        float w = wgs[hi + 2 * j];
        float4 v = xv[j];
        pn.x = fmaf(w, v.x, pn.x);
        pn.y = fmaf(w, v.y, pn.y);
        pn.z = fmaf(w, v.z, pn.z);
        pn.w = fmaf(w, v.w, pn.w);
        s  += v.x + v.y + v.z + v.w;
        s2 += v.x*v.x + v.y*v.y + v.z*v.z + v.w*v.w;
    }

    // combine the two channel-subsets for P
    if (hi == 1) pshare[lo] = pn;

    // warp-level stats reduction (independent of pshare)
    #pragma unroll
    for (int off = 16; off > 0; off >>= 1) {
        s  += __shfl_xor_sync(0xffffffffu, s,  off);
        s2 += __shfl_xor_sync(0xffffffffu, s2, off);
    }
    if (lane == 0) { sw[warp] = s; sw2[warp] = s2; }
    __syncthreads();

    if (hi == 0) {
        float4 t = pshare[lo];
        pn.x += t.x; pn.y += t.y; pn.z += t.z; pn.w += t.w;
        ((float4*)d_P)[bg * 256 + h * 128 + lo] = pn;
    }
    if (tid == 0) {
        float ts = 0.f, ts2 = 0.f;
        #pragma unroll
        for (int i = 0; i < 8; i++) { ts += sw[i]; ts2 += sw2[i]; }
        d_psum[blk]  = ts;
        d_psum2[blk] = ts2;
    }
}

// ============================================================
// Kernel 2: softmax mixture -> h2[b,n]
// grid 256, one warp per n-row
// ============================================================
__global__ void attn_kernel()
{
    int blk = blockIdx.x;
    int b  = blk >> 4;
    int n0 = (blk & 15) * ROWS;
    int tid = threadIdx.x;
    int warp = tid >> 5, lane = tid & 31;

    __shared__ float ks[FF], vs[FF];
    __shared__ float Ps[GG][ROWS + 1];
    __shared__ float Ss[ROWS];
    __shared__ float rstd_s[GG];
    __shared__ float red[20];

    for (int i = tid; i < FF; i += 256) {
        ks[i] = d_k[b * FF + i];
        vs[i] = d_v[b * FF + i];
    }
    for (int i = tid; i < GG * ROWS; i += 256) {
        int g = i >> 6, nn = i & (ROWS - 1);
        Ps[g][nn] = d_P[(size_t)(b * GG + g) * NN + n0 + nn];
    }
    // finalize group stats from per-half partials
    float mu_l = 0.f;
    if (tid < GG) {
        int base = (b * GG + tid) * 2;
        float ps  = d_psum [base] + d_psum [base + 1];
        float ps2 = d_psum2[base] + d_psum2[base + 1];
        float mean = ps * (1.f / 16384.f);
        float var  = ps2 * (1.f / 16384.f) - mean * mean;
        rstd_s[tid] = rsqrtf(var + EPSV);
        mu_l = mean;
    }
    __syncthreads();

    // per-b kmax/kmin + T[b]
    float km = -1e30f, kn = 1e30f;
    for (int i = tid; i < FF; i += 256) {
        float kk = ks[i];
        km = fmaxf(km, kk);
        kn = fminf(kn, kk);
    }
    #pragma unroll
    for (int off = 16; off > 0; off >>= 1) {
        km = fmaxf(km, __shfl_xor_sync(0xffffffffu, km, off));
        kn = fminf(kn, __shfl_xor_sync(0xffffffffu, kn, off));
    }
    if (lane == 0) { red[warp] = km; red[8 + warp] = kn; }
    float Tp = 0.f;
    if (tid < GG)
        Tp = -mu_l * rstd_s[tid] * d_wgsum[tid] + d_c0part[tid];
    if (warp == 0) {
        #pragma unroll
        for (int off = 16; off > 0; off >>= 1)
            Tp += __shfl_xor_sync(0xffffffffu, Tp, off);
        if (lane == 0) red[16] = Tp + d_bqsum;
    }
    __syncthreads();

    float kmax = red[0], kmin = red[8];
    #pragma unroll
    for (int i = 1; i < 8; i++) {
        kmax = fmaxf(kmax, red[i]);
        kmin = fminf(kmin, red[8 + i]);
    }
    float Tc = red[16];

    if (tid < ROWS) {
        float s = Tc;
        #pragma unroll
        for (int g = 0; g < GG; g++) s = fmaf(rstd_s[g], Ps[g][tid], s);
        Ss[tid] = SCALE * s;
    }
    __syncthreads();

    for (int r = warp; r < ROWS; r += 8) {
        float a = Ss[r];
        float shift = (a >= 0.f) ? a * kmax : a * kmin;
        float num = 0.f, den = 0.f;
        #pragma unroll
        for (int f = lane; f < FF; f += 32) {
            float e = __expf(fmaf(a, ks[f], -shift));
            den += e;
            num = fmaf(vs[f], e, num);
        }
        #pragma unroll
        for (int off = 16; off > 0; off >>= 1) {
            num += __shfl_xor_sync(0xffffffffu, num, off);
            den += __shfl_xor_sync(0xffffffffu, den, off);
        }
        if (lane == 0) d_h2[b * NN + n0 + r] = num / den;
    }
}

// ============================================================
// Kernel 3: y = x + h2[b,n]*wosum[o] + bo[o]
// R1 config: ILP=1, grid 8192, plain loads/stores (best measured: 11.2us)
// ============================================================
__global__ void out_kernel(const float* __restrict__ x,
                           const float* __restrict__ bo,
                           float* __restrict__ y)
{
    int i = blockIdx.x * 256 + threadIdx.x;   // over float4 (2,097,152)
    float4 xv = ((const float4*)x)[i];
    int n4   = i & 255;                       // NN/4 = 256
    int rest = i >> 8;
    int o = rest & 511;
    int b = rest >> 9;
    float4 h2 = ((const float4*)d_h2)[b * 256 + n4];
    float ws = d_wosum[o];
    float bias = bo[o];
    float4 r;
    r.x = fmaf(h2.x, ws, xv.x + bias);
    r.y = fmaf(h2.y, ws, xv.y + bias);
    r.z = fmaf(h2.z, ws, xv.z + bias);
    r.w = fmaf(h2.w, ws, xv.w + bias);
    ((float4*)y)[i] = r;
}

// ============================================================
extern "C" void kernel_launch(void* const* d_in, const int* in_sizes, int n_in,
                              void* d_out, int out_size)
{
    const float* x     = (const float*)d_in[0];
    const float* cond  = (const float*)d_in[1];
    const float* gamma = (const float*)d_in[2];
    const float* beta  = (const float*)d_in[3];
    const float* wq    = (const float*)d_in[4];
    const float* bq    = (const float*)d_in[5];
    const float* wk    = (const float*)d_in[6];
    const float* bk    = (const float*)d_in[7];
    const float* wv    = (const float*)d_in[8];
    const float* bv    = (const float*)d_in[9];
    const float* wo    = (const float*)d_in[10];
    const float* bo    = (const float*)d_in[11];
    float* y = (float*)d_out;

    prep_kernel<<<89, 256>>>(cond, gamma, beta, wq, bq, wk, bk, wv, bv, wo);
    gn_kernel<<<BB * GG * 2, 256>>>(x);
    attn_kernel<<<BB * (NN / ROWS), 256>>>();
    out_kernel<<<(BB * CC * NN) / (4 * 256), 256>>>(x, bo, y);
}